// round 2
// baseline (speedup 1.0000x reference)
#include <cuda_runtime.h>
#include <math.h>

#define B_    2
#define QLEN  2048
#define HID   2048
#define HQ    16
#define HKV   4
#define DH    128
#define QKVN  (HQ*DH + 2*HKV*DH)   /* 3072 */
#define NTOK  (B_*QLEN)            /* 4096 */

// ---------------- scratch (device globals: allocation-free) ----------------
__device__ float g_qkv [NTOK * QKVN];            // 50.3 MB
__device__ float g_q   [B_ * HQ  * QLEN * DH];   // 33.5 MB
__device__ float g_k   [B_ * HKV * QLEN * DH];   //  8.4 MB
__device__ float g_v   [B_ * HKV * QLEN * DH];   //  8.4 MB
__device__ float g_attn[NTOK * HQ * DH];         // 33.5 MB

// ---------------- SGEMM: C[M,N] = A[M,K] * B[N,K]^T (both row-major) -------
// 128x128 tile, BK=8, 256 threads, 8x8 per thread.
__global__ __launch_bounds__(256) void sgemm_nt(
    const float* __restrict__ A, const float* __restrict__ Bm,
    float* __restrict__ C, int M, int N, int K)
{
    __shared__ float As[8][128];
    __shared__ float Bs[8][128];
    int tid = threadIdx.x;
    int bm = blockIdx.y * 128;
    int bn = blockIdx.x * 128;
    int lr = tid >> 1;            // 0..127
    int lc = (tid & 1) * 4;       // 0 or 4
    const float* Ap = A  + (size_t)(bm + lr) * K + lc;
    const float* Bp = Bm + (size_t)(bn + lr) * K + lc;
    int ty = tid >> 4, tx = tid & 15;
    float acc[8][8];
    #pragma unroll
    for (int i = 0; i < 8; i++)
        #pragma unroll
        for (int j = 0; j < 8; j++) acc[i][j] = 0.f;

    for (int kt = 0; kt < K; kt += 8) {
        float4 av = *(const float4*)(Ap + kt);
        float4 bv = *(const float4*)(Bp + kt);
        As[lc+0][lr] = av.x; As[lc+1][lr] = av.y; As[lc+2][lr] = av.z; As[lc+3][lr] = av.w;
        Bs[lc+0][lr] = bv.x; Bs[lc+1][lr] = bv.y; Bs[lc+2][lr] = bv.z; Bs[lc+3][lr] = bv.w;
        __syncthreads();
        #pragma unroll
        for (int k = 0; k < 8; k++) {
            float4 a0 = *(const float4*)&As[k][ty*8];
            float4 a1 = *(const float4*)&As[k][ty*8+4];
            float4 b0 = *(const float4*)&Bs[k][tx*8];
            float4 b1 = *(const float4*)&Bs[k][tx*8+4];
            float ar[8] = {a0.x,a0.y,a0.z,a0.w,a1.x,a1.y,a1.z,a1.w};
            float br[8] = {b0.x,b0.y,b0.z,b0.w,b1.x,b1.y,b1.z,b1.w};
            #pragma unroll
            for (int i = 0; i < 8; i++)
                #pragma unroll
                for (int j = 0; j < 8; j++)
                    acc[i][j] = fmaf(ar[i], br[j], acc[i][j]);
        }
        __syncthreads();
    }
    #pragma unroll
    for (int i = 0; i < 8; i++) {
        float* crow = C + (size_t)(bm + ty*8 + i) * N + bn + tx*8;
        float4 v0; v0.x = acc[i][0]; v0.y = acc[i][1]; v0.z = acc[i][2]; v0.w = acc[i][3];
        float4 v1; v1.x = acc[i][4]; v1.y = acc[i][5]; v1.z = acc[i][6]; v1.w = acc[i][7];
        *(float4*)crow       = v0;
        *(float4*)(crow + 4) = v1;
    }
}

// ---------------- fused RMSNorm + RoPE + scatter to q/k/v ------------------
// grid (NTOK, 24): heads 0..15 = q, 16..19 = k, 20..23 = v. block = 128 (=DH)
__global__ __launch_bounds__(128) void rmsnorm_rope(
    const int* __restrict__ pos,
    const float* __restrict__ qw, const float* __restrict__ kw)
{
    int token = blockIdx.x;
    int h = blockIdx.y;
    int d = threadIdx.x;
    int b = token / QLEN, q = token % QLEN;

    if (h >= 20) {  // V: straight copy (entire block uniform)
        int hv = h - 20;
        g_v[(((size_t)b*HKV + hv)*QLEN + q)*DH + d] =
            g_qkv[(size_t)token*QKVN + HQ*DH + HKV*DH + hv*DH + d];
        return;
    }
    bool isq = (h < 16);
    int off = isq ? h*DH : HQ*DH + (h-16)*DH;
    float x = g_qkv[(size_t)token*QKVN + off + d];

    __shared__ float red[4];
    __shared__ float sx[128];
    float s = x * x;
    #pragma unroll
    for (int o = 16; o; o >>= 1) s += __shfl_xor_sync(0xffffffffu, s, o);
    if ((d & 31) == 0) red[d >> 5] = s;
    __syncthreads();
    float tot = red[0] + red[1] + red[2] + red[3];
    float r = rsqrtf(tot * (1.0f/DH) + 1e-6f);
    const float* w = isq ? qw : kw;
    float xn = x * r * w[d];
    sx[d] = xn;
    __syncthreads();

    float p = (float)pos[token];
    int i = d & 63;
    float invf = exp2f(-((float)i) * (log2f(1.0e6f) / 64.0f));
    float ang = p * invf;
    float c = cosf(ang), sn = sinf(ang);
    float outv = (d < 64) ? (sx[d]*c - sx[d+64]*sn)
                          : (sx[d]*c + sx[d-64]*sn);
    if (isq) g_q[(((size_t)b*HQ  + h     )*QLEN + q)*DH + d] = outv;
    else     g_k[(((size_t)b*HKV + (h-16))*QLEN + q)*DH + d] = outv;
}

// ---------------- flash attention (fp32, causal, GQA) ----------------------
#define FBM 64
#define FBN 64
#define SD  132   // padded row stride to break bank conflicts
#define FLASH_SMEM ((3*FBM*SD + FBM*65 + 3*FBM) * 4)

__global__ __launch_bounds__(256) void flash_attn()
{
    extern __shared__ float sm_[];
    float* sQ  = sm_;
    float* sK  = sQ + FBM*SD;
    float* sV  = sK + FBN*SD;
    float* sS  = sV + FBN*SD;       // FBM x 65
    float* sMx = sS + FBM*65;
    float* sL  = sMx + FBM;
    float* sA  = sL + FBM;

    int tid = threadIdx.x;
    int qt = blockIdx.x, h = blockIdx.y, b = blockIdx.z;
    int hkv = h >> 2;   // rep = 4

    const float* Qg = g_q + (((size_t)b*HQ  + h  )*QLEN + qt*FBM)*DH;
    const float* Kg = g_k + (((size_t)b*HKV + hkv)*QLEN)*DH;
    const float* Vg = g_v + (((size_t)b*HKV + hkv)*QLEN)*DH;

    #pragma unroll
    for (int it = 0; it < 8; it++) {
        int e = tid + it*256;
        int row = e >> 5, c4 = (e & 31) << 2;
        *(float4*)&sQ[row*SD + c4] = *(const float4*)&Qg[row*DH + c4];
    }
    if (tid < FBM) { sMx[tid] = -1e30f; sL[tid] = 0.f; }

    float o[8][4];
    #pragma unroll
    for (int i = 0; i < 8; i++)
        #pragma unroll
        for (int j = 0; j < 4; j++) o[i][j] = 0.f;

    int rg = tid >> 5;            // row group: 8 rows each
    int cg = (tid & 31) << 2;     // col base: 4 cols
    const float scale = 0.08838834764831845f;  // 1/sqrt(128)
    int ty = tid >> 4, tx = tid & 15;

    for (int kb = 0; kb <= qt; kb++) {
        __syncthreads();   // K/V smem reuse barrier (also covers Q-load on kb=0)
        #pragma unroll
        for (int it = 0; it < 8; it++) {
            int e = tid + it*256;
            int row = e >> 5, c4 = (e & 31) << 2;
            *(float4*)&sK[row*SD + c4] = *(const float4*)&Kg[((size_t)kb*FBN + row)*DH + c4];
            *(float4*)&sV[row*SD + c4] = *(const float4*)&Vg[((size_t)kb*FBN + row)*DH + c4];
        }
        __syncthreads();

        // S = Q K^T : thread computes 4x4 tile
        float acc[4][4];
        #pragma unroll
        for (int a = 0; a < 4; a++)
            #pragma unroll
            for (int c = 0; c < 4; c++) acc[a][c] = 0.f;
        #pragma unroll 4
        for (int k = 0; k < DH; k += 4) {
            float4 qv[4], kv[4];
            #pragma unroll
            for (int a = 0; a < 4; a++) qv[a] = *(const float4*)&sQ[(ty*4+a)*SD + k];
            #pragma unroll
            for (int c = 0; c < 4; c++) kv[c] = *(const float4*)&sK[(tx*4+c)*SD + k];
            #pragma unroll
            for (int a = 0; a < 4; a++)
                #pragma unroll
                for (int c = 0; c < 4; c++)
                    acc[a][c] += qv[a].x*kv[c].x + qv[a].y*kv[c].y
                               + qv[a].z*kv[c].z + qv[a].w*kv[c].w;
        }
        #pragma unroll
        for (int a = 0; a < 4; a++) {
            int grow = qt*FBM + ty*4 + a;
            #pragma unroll
            for (int c = 0; c < 4; c++) {
                int gcol = kb*FBN + tx*4 + c;
                sS[(ty*4+a)*65 + tx*4+c] = (gcol <= grow) ? acc[a][c]*scale : -1e30f;
            }
        }
        __syncthreads();

        // online softmax, one thread per row
        if (tid < FBM) {
            int i = tid;
            float m = sMx[i], mn = m;
            #pragma unroll 8
            for (int j = 0; j < FBN; j++) mn = fmaxf(mn, sS[i*65+j]);
            float al = __expf(m - mn);
            float sum = 0.f;
            #pragma unroll 8
            for (int j = 0; j < FBN; j++) {
                float pij = __expf(sS[i*65+j] - mn);
                sS[i*65+j] = pij;
                sum += pij;
            }
            sL[i] = sL[i]*al + sum;
            sMx[i] = mn;
            sA[i] = al;
        }
        __syncthreads();

        // O = O*alpha + P*V
        #pragma unroll
        for (int i = 0; i < 8; i++) {
            float al = sA[rg*8 + i];
            #pragma unroll
            for (int c = 0; c < 4; c++) o[i][c] *= al;
        }
        #pragma unroll 4
        for (int j = 0; j < FBN; j++) {
            float4 v4 = *(const float4*)&sV[j*SD + cg];
            #pragma unroll
            for (int i = 0; i < 8; i++) {
                float p = sS[(rg*8+i)*65 + j];
                o[i][0] = fmaf(p, v4.x, o[i][0]);
                o[i][1] = fmaf(p, v4.y, o[i][1]);
                o[i][2] = fmaf(p, v4.z, o[i][2]);
                o[i][3] = fmaf(p, v4.w, o[i][3]);
            }
        }
    }
    __syncthreads();

    #pragma unroll
    for (int i = 0; i < 8; i++) {
        int row = rg*8 + i;
        float inv = 1.0f / sL[row];
        int q = qt*FBM + row;
        float4 v;
        v.x = o[i][0]*inv; v.y = o[i][1]*inv; v.z = o[i][2]*inv; v.w = o[i][3]*inv;
        *(float4*)&g_attn[((size_t)(b*QLEN + q))*(HQ*DH) + h*DH + cg] = v;
    }
}

// ---------------------------------------------------------------------------
extern "C" void kernel_launch(void* const* d_in, const int* in_sizes, int n_in,
                              void* d_out, int out_size)
{
    const int*   positions = (const int*)  d_in[0];
    const float* hidden    = (const float*)d_in[1];
    // d_in[2]=k_cache, d_in[3]=v_cache: zeros with start=0 -> fully overwritten, unused
    const float* wqkv      = (const float*)d_in[4];
    const float* wo        = (const float*)d_in[5];
    const float* qw        = (const float*)d_in[6];
    const float* kw        = (const float*)d_in[7];
    float* out = (float*)d_out;

    float *p_qkv, *p_attn;
    cudaGetSymbolAddress((void**)&p_qkv,  g_qkv);
    cudaGetSymbolAddress((void**)&p_attn, g_attn);

    // 1) QKV projection: [4096,3072] = hidden[4096,2048] @ wqkv^T
    sgemm_nt<<<dim3(QKVN/128, NTOK/128), 256>>>(hidden, wqkv, p_qkv, NTOK, QKVN, HID);

    // 2) RMSNorm + RoPE + scatter
    rmsnorm_rope<<<dim3(NTOK, 24), 128>>>(positions, qw, kw);

    // 3) causal GQA flash attention
    cudaFuncSetAttribute(flash_attn, cudaFuncAttributeMaxDynamicSharedMemorySize, FLASH_SMEM);
    flash_attn<<<dim3(QLEN/FBM, HQ, B_), 256, FLASH_SMEM>>>();

    // 4) output projection: [4096,2048] = attn[4096,2048] @ wo^T
    sgemm_nt<<<dim3(HID/128, NTOK/128), 256>>>(p_attn, wo, out, NTOK, HID, HID);
}

// round 3
// speedup vs baseline: 1.0003x; 1.0003x over previous
#include <cuda_runtime.h>
#include <math.h>

#define B_    2
#define QLEN  2048
#define HID   2048
#define HQ    16
#define HKV   4
#define DH    128
#define QKVN  (HQ*DH + 2*HKV*DH)   /* 3072 */
#define NTOK  (B_*QLEN)            /* 4096 */

// ---------------- scratch (device globals: allocation-free) ----------------
__device__ float g_qkv [NTOK * QKVN];            // 50.3 MB
__device__ float g_q   [B_ * HQ  * QLEN * DH];   // 33.5 MB
__device__ float g_k   [B_ * HKV * QLEN * DH];   //  8.4 MB
__device__ float g_v   [B_ * HKV * QLEN * DH];   //  8.4 MB
__device__ float g_attn[NTOK * HQ * DH];         // 33.5 MB

// ---------------- SGEMM: C[M,N] = A[M,K] * B[N,K]^T (both row-major) -------
// 128x128 tile, BK=8, 256 threads, 8x8 per thread.
__global__ __launch_bounds__(256) void sgemm_nt(
    const float* __restrict__ A, const float* __restrict__ Bm,
    float* __restrict__ C, int M, int N, int K)
{
    __shared__ float As[8][128];
    __shared__ float Bs[8][128];
    int tid = threadIdx.x;
    int bm = blockIdx.y * 128;
    int bn = blockIdx.x * 128;
    int lr = tid >> 1;            // 0..127
    int lc = (tid & 1) * 4;       // 0 or 4
    const float* Ap = A  + (size_t)(bm + lr) * K + lc;
    const float* Bp = Bm + (size_t)(bn + lr) * K + lc;
    int ty = tid >> 4, tx = tid & 15;
    float acc[8][8];
    #pragma unroll
    for (int i = 0; i < 8; i++)
        #pragma unroll
        for (int j = 0; j < 8; j++) acc[i][j] = 0.f;

    for (int kt = 0; kt < K; kt += 8) {
        float4 av = *(const float4*)(Ap + kt);
        float4 bv = *(const float4*)(Bp + kt);
        As[lc+0][lr] = av.x; As[lc+1][lr] = av.y; As[lc+2][lr] = av.z; As[lc+3][lr] = av.w;
        Bs[lc+0][lr] = bv.x; Bs[lc+1][lr] = bv.y; Bs[lc+2][lr] = bv.z; Bs[lc+3][lr] = bv.w;
        __syncthreads();
        #pragma unroll
        for (int k = 0; k < 8; k++) {
            float4 a0 = *(const float4*)&As[k][ty*8];
            float4 a1 = *(const float4*)&As[k][ty*8+4];
            float4 b0 = *(const float4*)&Bs[k][tx*8];
            float4 b1 = *(const float4*)&Bs[k][tx*8+4];
            float ar[8] = {a0.x,a0.y,a0.z,a0.w,a1.x,a1.y,a1.z,a1.w};
            float br[8] = {b0.x,b0.y,b0.z,b0.w,b1.x,b1.y,b1.z,b1.w};
            #pragma unroll
            for (int i = 0; i < 8; i++)
                #pragma unroll
                for (int j = 0; j < 8; j++)
                    acc[i][j] = fmaf(ar[i], br[j], acc[i][j]);
        }
        __syncthreads();
    }
    #pragma unroll
    for (int i = 0; i < 8; i++) {
        float* crow = C + (size_t)(bm + ty*8 + i) * N + bn + tx*8;
        float4 v0; v0.x = acc[i][0]; v0.y = acc[i][1]; v0.z = acc[i][2]; v0.w = acc[i][3];
        float4 v1; v1.x = acc[i][4]; v1.y = acc[i][5]; v1.z = acc[i][6]; v1.w = acc[i][7];
        *(float4*)crow       = v0;
        *(float4*)(crow + 4) = v1;
    }
}

// ---------------- fused RMSNorm + RoPE + scatter to q/k/v ------------------
// grid (NTOK, 24): heads 0..15 = q, 16..19 = k, 20..23 = v. block = 128 (=DH)
__global__ __launch_bounds__(128) void rmsnorm_rope(
    const int* __restrict__ pos,
    const float* __restrict__ qw, const float* __restrict__ kw)
{
    int token = blockIdx.x;
    int h = blockIdx.y;
    int d = threadIdx.x;
    int b = token / QLEN, q = token % QLEN;

    if (h >= 20) {  // V: straight copy (entire block uniform)
        int hv = h - 20;
        g_v[(((size_t)b*HKV + hv)*QLEN + q)*DH + d] =
            g_qkv[(size_t)token*QKVN + HQ*DH + HKV*DH + hv*DH + d];
        return;
    }
    bool isq = (h < 16);
    int off = isq ? h*DH : HQ*DH + (h-16)*DH;
    float x = g_qkv[(size_t)token*QKVN + off + d];

    __shared__ float red[4];
    __shared__ float sx[128];
    float s = x * x;
    #pragma unroll
    for (int o = 16; o; o >>= 1) s += __shfl_xor_sync(0xffffffffu, s, o);
    if ((d & 31) == 0) red[d >> 5] = s;
    __syncthreads();
    float tot = red[0] + red[1] + red[2] + red[3];
    float r = rsqrtf(tot * (1.0f/DH) + 1e-6f);
    const float* w = isq ? qw : kw;
    float xn = x * r * w[d];
    sx[d] = xn;
    __syncthreads();

    float p = (float)pos[token];
    int i = d & 63;
    float invf = exp2f(-((float)i) * (log2f(1.0e6f) / 64.0f));
    float ang = p * invf;
    float c = cosf(ang), sn = sinf(ang);
    float outv = (d < 64) ? (sx[d]*c - sx[d+64]*sn)
                          : (sx[d]*c + sx[d-64]*sn);
    if (isq) g_q[(((size_t)b*HQ  + h     )*QLEN + q)*DH + d] = outv;
    else     g_k[(((size_t)b*HKV + (h-16))*QLEN + q)*DH + d] = outv;
}

// ---------------- flash attention (fp32, causal, GQA) ----------------------
#define FBM 64
#define FBN 64
#define SD  132   // padded row stride to break bank conflicts
#define FLASH_SMEM ((3*FBM*SD + FBM*65 + 3*FBM) * 4)

__global__ __launch_bounds__(256) void flash_attn()
{
    extern __shared__ float sm_[];
    float* sQ  = sm_;
    float* sK  = sQ + FBM*SD;
    float* sV  = sK + FBN*SD;
    float* sS  = sV + FBN*SD;       // FBM x 65
    float* sMx = sS + FBM*65;
    float* sL  = sMx + FBM;
    float* sA  = sL + FBM;

    int tid = threadIdx.x;
    int qt = blockIdx.x, h = blockIdx.y, b = blockIdx.z;
    int hkv = h >> 2;   // rep = 4

    const float* Qg = g_q + (((size_t)b*HQ  + h  )*QLEN + qt*FBM)*DH;
    const float* Kg = g_k + (((size_t)b*HKV + hkv)*QLEN)*DH;
    const float* Vg = g_v + (((size_t)b*HKV + hkv)*QLEN)*DH;

    #pragma unroll
    for (int it = 0; it < 8; it++) {
        int e = tid + it*256;
        int row = e >> 5, c4 = (e & 31) << 2;
        *(float4*)&sQ[row*SD + c4] = *(const float4*)&Qg[row*DH + c4];
    }
    if (tid < FBM) { sMx[tid] = -1e30f; sL[tid] = 0.f; }

    float o[8][4];
    #pragma unroll
    for (int i = 0; i < 8; i++)
        #pragma unroll
        for (int j = 0; j < 4; j++) o[i][j] = 0.f;

    int rg = tid >> 5;            // row group: 8 rows each
    int cg = (tid & 31) << 2;     // col base: 4 cols
    const float scale = 0.08838834764831845f;  // 1/sqrt(128)
    int ty = tid >> 4, tx = tid & 15;

    for (int kb = 0; kb <= qt; kb++) {
        __syncthreads();   // K/V smem reuse barrier (also covers Q-load on kb=0)
        #pragma unroll
        for (int it = 0; it < 8; it++) {
            int e = tid + it*256;
            int row = e >> 5, c4 = (e & 31) << 2;
            *(float4*)&sK[row*SD + c4] = *(const float4*)&Kg[((size_t)kb*FBN + row)*DH + c4];
            *(float4*)&sV[row*SD + c4] = *(const float4*)&Vg[((size_t)kb*FBN + row)*DH + c4];
        }
        __syncthreads();

        // S = Q K^T : thread computes 4x4 tile
        float acc[4][4];
        #pragma unroll
        for (int a = 0; a < 4; a++)
            #pragma unroll
            for (int c = 0; c < 4; c++) acc[a][c] = 0.f;
        #pragma unroll 4
        for (int k = 0; k < DH; k += 4) {
            float4 qv[4], kv[4];
            #pragma unroll
            for (int a = 0; a < 4; a++) qv[a] = *(const float4*)&sQ[(ty*4+a)*SD + k];
            #pragma unroll
            for (int c = 0; c < 4; c++) kv[c] = *(const float4*)&sK[(tx*4+c)*SD + k];
            #pragma unroll
            for (int a = 0; a < 4; a++)
                #pragma unroll
                for (int c = 0; c < 4; c++)
                    acc[a][c] += qv[a].x*kv[c].x + qv[a].y*kv[c].y
                               + qv[a].z*kv[c].z + qv[a].w*kv[c].w;
        }
        #pragma unroll
        for (int a = 0; a < 4; a++) {
            int grow = qt*FBM + ty*4 + a;
            #pragma unroll
            for (int c = 0; c < 4; c++) {
                int gcol = kb*FBN + tx*4 + c;
                sS[(ty*4+a)*65 + tx*4+c] = (gcol <= grow) ? acc[a][c]*scale : -1e30f;
            }
        }
        __syncthreads();

        // online softmax, one thread per row
        if (tid < FBM) {
            int i = tid;
            float m = sMx[i], mn = m;
            #pragma unroll 8
            for (int j = 0; j < FBN; j++) mn = fmaxf(mn, sS[i*65+j]);
            float al = __expf(m - mn);
            float sum = 0.f;
            #pragma unroll 8
            for (int j = 0; j < FBN; j++) {
                float pij = __expf(sS[i*65+j] - mn);
                sS[i*65+j] = pij;
                sum += pij;
            }
            sL[i] = sL[i]*al + sum;
            sMx[i] = mn;
            sA[i] = al;
        }
        __syncthreads();

        // O = O*alpha + P*V
        #pragma unroll
        for (int i = 0; i < 8; i++) {
            float al = sA[rg*8 + i];
            #pragma unroll
            for (int c = 0; c < 4; c++) o[i][c] *= al;
        }
        #pragma unroll 4
        for (int j = 0; j < FBN; j++) {
            float4 v4 = *(const float4*)&sV[j*SD + cg];
            #pragma unroll
            for (int i = 0; i < 8; i++) {
                float p = sS[(rg*8+i)*65 + j];
                o[i][0] = fmaf(p, v4.x, o[i][0]);
                o[i][1] = fmaf(p, v4.y, o[i][1]);
                o[i][2] = fmaf(p, v4.z, o[i][2]);
                o[i][3] = fmaf(p, v4.w, o[i][3]);
            }
        }
    }
    __syncthreads();

    #pragma unroll
    for (int i = 0; i < 8; i++) {
        int row = rg*8 + i;
        float inv = 1.0f / sL[row];
        int q = qt*FBM + row;
        float4 v;
        v.x = o[i][0]*inv; v.y = o[i][1]*inv; v.z = o[i][2]*inv; v.w = o[i][3]*inv;
        *(float4*)&g_attn[((size_t)(b*QLEN + q))*(HQ*DH) + h*DH + cg] = v;
    }
}

// ---------------------------------------------------------------------------
extern "C" void kernel_launch(void* const* d_in, const int* in_sizes, int n_in,
                              void* d_out, int out_size)
{
    const int*   positions = (const int*)  d_in[0];
    const float* hidden    = (const float*)d_in[1];
    // d_in[2]=k_cache, d_in[3]=v_cache: zeros with start=0 -> fully overwritten, unused
    const float* wqkv      = (const float*)d_in[4];
    const float* wo        = (const float*)d_in[5];
    const float* qw        = (const float*)d_in[6];
    const float* kw        = (const float*)d_in[7];
    float* out = (float*)d_out;

    float *p_qkv, *p_attn;
    cudaGetSymbolAddress((void**)&p_qkv,  g_qkv);
    cudaGetSymbolAddress((void**)&p_attn, g_attn);

    // 1) QKV projection: [4096,3072] = hidden[4096,2048] @ wqkv^T
    sgemm_nt<<<dim3(QKVN/128, NTOK/128), 256>>>(hidden, wqkv, p_qkv, NTOK, QKVN, HID);

    // 2) RMSNorm + RoPE + scatter
    rmsnorm_rope<<<dim3(NTOK, 24), 128>>>(positions, qw, kw);

    // 3) causal GQA flash attention
    cudaFuncSetAttribute(flash_attn, cudaFuncAttributeMaxDynamicSharedMemorySize, FLASH_SMEM);
    flash_attn<<<dim3(QLEN/FBM, HQ, B_), 256, FLASH_SMEM>>>();

    // 4) output projection: [4096,2048] = attn[4096,2048] @ wo^T
    sgemm_nt<<<dim3(HID/128, NTOK/128), 256>>>(p_attn, wo, out, NTOK, HID, HID);
}